// round 1
// baseline (speedup 1.0000x reference)
#include <cuda_runtime.h>

#define B  32
#define P  16384
#define O  16
#define NC 80

// ---------------- device scratch (no allocations allowed) ----------------
__device__ float              g_overlap[B * P];
__device__ int                g_bidx[B * P];
__device__ unsigned long long g_bestprior[B * O];
__device__ float              g_sum_ll;
__device__ float              g_sum_lc;
__device__ int                g_poscnt;

// ---------------- helpers ----------------
__device__ __forceinline__ float focal_f(float x, bool tpos) {
    // focal loss, F_ALPHA=0.25, F_GAMMA=1.0 (so pt**gamma == pt)
    float ax = fabsf(x);
    float e  = __expf(-ax);          // exp(-|x|)
    float u  = 1.0f + e;
    float lp = __logf(u);            // log1p(exp(-|x|)), e in (0,1] so safe
    float p  = __fdividef((x >= 0.f) ? 1.0f : e, u);   // sigmoid(x), stable
    float bce, w;
    if (tpos) { bce = fmaxf(x, 0.f) - x + lp; w = 0.25f * (1.f - p); }
    else      { bce = fmaxf(x, 0.f)     + lp; w = 0.75f * p;         }
    return bce * w;
}

__device__ __forceinline__ float bl1(float diff) {
    // balanced L1, R_ALPHA=0.5, R_GAMMA=1.5, R_BETA=0.11, b = e^3 - 1
    const float bb = 19.085537f;
    float d = fabsf(diff);
    if (d < 0.11f) {
        return (0.5f / bb) * (bb * d + 1.f) * log1pf(bb * d * (1.0f / 0.11f)) - 0.5f * d;
    }
    return 1.5f * d + (1.5f / bb - 0.5f * 0.11f);
}

// ---------------- kernels ----------------
__global__ void k_init() {
    int i = threadIdx.x;
    if (i < B * O) g_bestprior[i] = 0ull;
    if (i == 0) { g_sum_ll = 0.f; g_sum_lc = 0.f; g_poscnt = 0; }
}

// one block per 256 priors, gridDim.y = batch
__global__ void k_match(const float4* __restrict__ priors,
                        const float*  __restrict__ targets) {
    __shared__ float4             s_tr[O];
    __shared__ float              s_area[O];
    __shared__ unsigned long long s_key[O];

    int tid = threadIdx.x;
    int b   = blockIdx.y;
    int p   = blockIdx.x * blockDim.x + tid;

    if (tid < O) {
        const float* t = targets + (b * O + tid) * 5;
        float4 tr = make_float4(t[0], t[1], t[2], t[3]);   // already point-form
        s_tr[tid]   = tr;
        s_area[tid] = (tr.z - tr.x) * (tr.w - tr.y);
        s_key[tid]  = 0ull;
    }
    __syncthreads();

    float4 pr = priors[p];                 // cx, cy, w, h
    float px0 = pr.x - pr.z * 0.5f;
    float py0 = pr.y - pr.w * 0.5f;
    float px1 = pr.x + pr.z * 0.5f;
    float py1 = pr.y + pr.w * 0.5f;
    float areaB = (px1 - px0) * (py1 - py0);

    float best = -1.f;
    int   bidx = 0;
    #pragma unroll
    for (int j = 0; j < O; j++) {
        float4 tr = s_tr[j];
        float ix = fminf(tr.z, px1) - fmaxf(tr.x, px0);
        float iy = fminf(tr.w, py1) - fmaxf(tr.y, py0);
        ix = fmaxf(ix, 0.f);
        iy = fmaxf(iy, 0.f);
        float inter = ix * iy;
        float iou   = inter / (s_area[j] + areaB - inter);
        if (iou > best) { best = iou; bidx = j; }   // first-max wins (JAX argmax)
        // per-truth best prior: max IoU, ties -> smallest p (JAX argmax)
        unsigned long long key =
            ((unsigned long long)__float_as_uint(iou) << 32) |
            (unsigned)(0xFFFFFFFFu - (unsigned)p);
        atomicMax(&s_key[j], key);
    }

    g_overlap[b * P + p] = best;
    g_bidx[b * P + p]    = bidx;

    __syncthreads();
    if (tid < O) atomicMax(&g_bestprior[b * O + tid], s_key[tid]);
}

// force-match each truth's best prior; serial over truths (last wins, like XLA scatter)
__global__ void k_override() {
    int b = threadIdx.x;
    if (b >= B) return;
    for (int j = 0; j < O; j++) {
        unsigned long long key = g_bestprior[b * O + j];
        unsigned p = 0xFFFFFFFFu - (unsigned)(key & 0xFFFFFFFFull);
        g_overlap[b * P + p] = 2.0f;
        g_bidx[b * P + p]    = j;
    }
}

// thread i handles float4 i of conf_data (4 classes); 20 float4 per prior.
// c4==0 thread additionally handles the loc loss + pos count for its prior.
__global__ void k_loss(const float4* __restrict__ conf4,
                       const float4* __restrict__ loc4,
                       const float4* __restrict__ priors,
                       const float*  __restrict__ targets) {
    int i  = blockIdx.x * blockDim.x + threadIdx.x;   // == conf4 index
    int bp = i / 20;                                   // b*P + prior
    int c4 = i - bp * 20;

    float ov   = g_overlap[bp];
    bool  pos  = ov >= 0.5f;
    bool  valid = pos || (ov < 0.4f);

    float lc = 0.f, ll = 0.f;
    int   pc = 0;

    int j = g_bidx[bp];
    int b = bp >> 14;                                  // P = 16384

    if (valid) {
        int tc = 0;
        if (pos) tc = (int)targets[(b * O + j) * 5 + 4] + 1;
        float4 x = conf4[i];
        int c = c4 * 4 + 1;
        lc  = focal_f(x.x, tc == c);
        lc += focal_f(x.y, tc == c + 1);
        lc += focal_f(x.z, tc == c + 2);
        lc += focal_f(x.w, tc == c + 3);
    }

    if (c4 == 0 && pos) {
        pc = 1;
        const float* t = targets + (b * O + j) * 5;
        float m0 = t[0], m1 = t[1], m2 = t[2], m3 = t[3];
        int pr_i = bp & (P - 1);
        float4 pp = priors[pr_i];
        float ex = ((m0 + m2) * 0.5f - pp.x) / (0.1f * pp.z);
        float ey = ((m1 + m3) * 0.5f - pp.y) / (0.1f * pp.w);
        float ew = __logf((m2 - m0) / pp.z) * 5.0f;    // /0.2
        float eh = __logf((m3 - m1) / pp.w) * 5.0f;
        float4 ld = loc4[bp];
        ll = bl1(ld.x - ex) + bl1(ld.y - ey) + bl1(ld.z - ew) + bl1(ld.w - eh);
    }

    // ---- block reduction ----
    #pragma unroll
    for (int o = 16; o; o >>= 1) {
        lc += __shfl_down_sync(0xFFFFFFFFu, lc, o);
        ll += __shfl_down_sync(0xFFFFFFFFu, ll, o);
        pc += __shfl_down_sync(0xFFFFFFFFu, pc, o);
    }
    __shared__ float s_lc[8], s_ll[8];
    __shared__ int   s_pc[8];
    int wid = threadIdx.x >> 5, lane = threadIdx.x & 31;
    if (lane == 0) { s_lc[wid] = lc; s_ll[wid] = ll; s_pc[wid] = pc; }
    __syncthreads();
    if (wid == 0) {
        lc = (lane < 8) ? s_lc[lane] : 0.f;
        ll = (lane < 8) ? s_ll[lane] : 0.f;
        pc = (lane < 8) ? s_pc[lane] : 0;
        #pragma unroll
        for (int o = 4; o; o >>= 1) {
            lc += __shfl_down_sync(0xFFFFFFFFu, lc, o);
            ll += __shfl_down_sync(0xFFFFFFFFu, ll, o);
            pc += __shfl_down_sync(0xFFFFFFFFu, pc, o);
        }
        if (lane == 0) {
            if (lc != 0.f) atomicAdd(&g_sum_lc, lc);
            if (ll != 0.f) atomicAdd(&g_sum_ll, ll);
            if (pc)        atomicAdd(&g_poscnt, pc);
        }
    }
}

__global__ void k_final(float* __restrict__ out) {
    float pn = fmaxf((float)g_poscnt, 1.0f);
    out[0] = g_sum_ll / (pn * 4.0f);
    out[1] = g_sum_lc / pn;
}

// ---------------- launch ----------------
extern "C" void kernel_launch(void* const* d_in, const int* in_sizes, int n_in,
                              void* d_out, int out_size) {
    const float4* loc4    = (const float4*)d_in[0];   // (B,P,4)  f32
    const float4* conf4   = (const float4*)d_in[1];   // (B,P,80) f32
    const float4* priors4 = (const float4*)d_in[2];   // (P,4)    f32
    const float*  targets = (const float*)d_in[3];    // (B,O,5)  f32
    float* out = (float*)d_out;

    k_init<<<1, 512>>>();
    dim3 mg(P / 256, B);
    k_match<<<mg, 256>>>(priors4, targets);
    k_override<<<1, 32>>>();
    int total4 = B * P * (NC / 4);                    // 10,485,760 float4
    k_loss<<<total4 / 256, 256>>>(conf4, loc4, priors4, targets);
    k_final<<<1, 1>>>(out);
}

// round 2
// speedup vs baseline: 1.4212x; 1.4212x over previous
#include <cuda_runtime.h>

#define B  32
#define P  16384
#define O  16
#define NC 80
#define TOTAL4 (B * P * (NC / 4))      // 10,485,760 float4 of conf

// ---------------- device scratch (no allocations allowed) ----------------
__device__ float              g_overlap[B * P];
__device__ int                g_bidx[B * P];
__device__ unsigned char      g_valid[B * P];
__device__ unsigned long long g_bestprior[B * O];
__device__ float              g_sum_ll;      // loc loss sum
__device__ float              g_sum_lcraw;   // sum of sigmoid*softplus (t=0 form, no 0.75)
__device__ float              g_sum_corr;    // per-pos-prior target-class correction (true units)
__device__ int                g_poscnt;

// ---------------- helpers ----------------
// g0raw(x) = sigmoid(x) * softplus(x)   [focal(x, t=0) == 0.75 * g0raw(x)]
// Uses sigmoid(x) = 1 - exp(-softplus(x)):  3 MUFU, no divide, no selects.
__device__ __forceinline__ float g0raw(float x) {
    float e = __expf(-fabsf(x));          // exp(-|x|) in (0,1]
    float L = __logf(1.0f + e);           // log1p(exp(-|x|))
    float h = fmaxf(x, 0.0f) + L;         // softplus(x)
    float q = __expf(-h);                 // = 1 - sigmoid(x)
    return fmaf(-h, q, h);                // h * (1 - q)
}

__device__ __forceinline__ float bl1(float diff) {
    // balanced L1, R_ALPHA=0.5, R_GAMMA=1.5, R_BETA=0.11, b = e^3 - 1
    const float bb = 19.085537f;
    float d = fabsf(diff);
    if (d < 0.11f) {
        return (0.5f / bb) * (bb * d + 1.f) * log1pf(bb * d * (1.0f / 0.11f)) - 0.5f * d;
    }
    return 1.5f * d + (1.5f / bb - 0.5f * 0.11f);
}

// ---------------- kernels ----------------
// one block per 256 priors, gridDim.y = batch
__global__ void k_match(const float4* __restrict__ priors,
                        const float*  __restrict__ targets) {
    __shared__ float4             s_tr[O];
    __shared__ float              s_area[O];
    __shared__ unsigned long long s_key[O];

    int tid = threadIdx.x;
    int b   = blockIdx.y;
    int p   = blockIdx.x * blockDim.x + tid;

    if (tid < O) {
        const float* t = targets + (b * O + tid) * 5;
        float4 tr = make_float4(t[0], t[1], t[2], t[3]);   // already point-form
        s_tr[tid]   = tr;
        s_area[tid] = (tr.z - tr.x) * (tr.w - tr.y);
        s_key[tid]  = 0ull;
    }
    __syncthreads();

    float4 pr = priors[p];                 // cx, cy, w, h
    float px0 = pr.x - pr.z * 0.5f;
    float py0 = pr.y - pr.w * 0.5f;
    float px1 = pr.x + pr.z * 0.5f;
    float py1 = pr.y + pr.w * 0.5f;
    float areaB = (px1 - px0) * (py1 - py0);

    float best = -1.f;
    int   bidx = 0;
    #pragma unroll
    for (int j = 0; j < O; j++) {
        float4 tr = s_tr[j];
        float ix = fminf(tr.z, px1) - fmaxf(tr.x, px0);
        float iy = fminf(tr.w, py1) - fmaxf(tr.y, py0);
        ix = fmaxf(ix, 0.f);
        iy = fmaxf(iy, 0.f);
        float inter = ix * iy;
        float iou   = inter / (s_area[j] + areaB - inter);
        if (iou > best) { best = iou; bidx = j; }   // first-max wins (JAX argmax)
        // per-truth best prior: max IoU, ties -> smallest p (JAX argmax)
        unsigned long long key =
            ((unsigned long long)__float_as_uint(iou) << 32) |
            (unsigned)(0xFFFFFFFFu - (unsigned)p);
        if (key > s_key[j]) atomicMax(&s_key[j], key);   // guarded: cuts contention
    }

    g_overlap[b * P + p] = best;
    g_bidx[b * P + p]    = bidx;

    __syncthreads();
    if (tid < O) {
        unsigned long long key = s_key[tid];
        if (key > g_bestprior[b * O + tid])
            atomicMax(&g_bestprior[b * O + tid], key);
    }
}

// force-match each truth's best prior; serial over truths (last wins, like XLA scatter)
__global__ void k_override() {
    int b = threadIdx.x;
    if (b >= B) return;
    for (int j = 0; j < O; j++) {
        unsigned long long key = g_bestprior[b * O + j];
        unsigned p = 0xFFFFFFFFu - (unsigned)(key & 0xFFFFFFFFull);
        g_overlap[b * P + p] = 2.0f;
        g_bidx[b * P + p]    = j;
    }
}

// per-prior metadata: validity byte, loc loss, pos count, focal target-class correction
__global__ void k_meta(const float4* __restrict__ loc4,
                       const float4* __restrict__ priors,
                       const float*  __restrict__ targets,
                       const float*  __restrict__ conf) {
    int bp = blockIdx.x * blockDim.x + threadIdx.x;   // b*P + prior
    float ov  = g_overlap[bp];
    bool pos  = ov >= 0.5f;
    bool valid = pos || (ov < 0.4f);
    g_valid[bp] = valid ? 1 : 0;

    float ll = 0.f, corr = 0.f;
    int pc = 0;
    if (pos) {
        pc = 1;
        int b = bp >> 14;                 // P = 16384
        int j = g_bidx[bp];
        const float* t = targets + (b * O + j) * 5;
        float m0 = t[0], m1 = t[1], m2 = t[2], m3 = t[3];
        int tc = (int)t[4] + 1;           // 1..80

        int pr_i = bp & (P - 1);
        float4 pp = priors[pr_i];
        float ex = ((m0 + m2) * 0.5f - pp.x) / (0.1f * pp.z);
        float ey = ((m1 + m3) * 0.5f - pp.y) / (0.1f * pp.w);
        float ew = __logf((m2 - m0) / pp.z) * 5.0f;   // /0.2
        float eh = __logf((m3 - m1) / pp.w) * 5.0f;
        float4 ld = loc4[bp];
        ll = bl1(ld.x - ex) + bl1(ld.y - ey) + bl1(ld.z - ew) + bl1(ld.w - eh);

        // correction: replace focal(x,0)=0.75*g0raw(x) by focal(x,1)=0.25*g0raw(-x)
        float x = conf[bp * NC + (tc - 1)];
        corr = 0.25f * g0raw(-x) - 0.75f * g0raw(x);
    }

    // block reduction (most blocks have few/no pos priors)
    #pragma unroll
    for (int o = 16; o; o >>= 1) {
        ll   += __shfl_down_sync(0xFFFFFFFFu, ll, o);
        corr += __shfl_down_sync(0xFFFFFFFFu, corr, o);
        pc   += __shfl_down_sync(0xFFFFFFFFu, pc, o);
    }
    __shared__ float s_ll[8], s_co[8];
    __shared__ int   s_pc[8];
    int wid = threadIdx.x >> 5, lane = threadIdx.x & 31;
    if (lane == 0) { s_ll[wid] = ll; s_co[wid] = corr; s_pc[wid] = pc; }
    __syncthreads();
    if (wid == 0) {
        ll   = (lane < 8) ? s_ll[lane] : 0.f;
        corr = (lane < 8) ? s_co[lane] : 0.f;
        pc   = (lane < 8) ? s_pc[lane] : 0;
        #pragma unroll
        for (int o = 4; o; o >>= 1) {
            ll   += __shfl_down_sync(0xFFFFFFFFu, ll, o);
            corr += __shfl_down_sync(0xFFFFFFFFu, corr, o);
            pc   += __shfl_down_sync(0xFFFFFFFFu, pc, o);
        }
        if (lane == 0 && pc) {
            atomicAdd(&g_sum_ll, ll);
            atomicAdd(&g_sum_corr, corr);
            atomicAdd(&g_poscnt, pc);
        }
    }
}

// streaming focal: every valid element computed as t=0, branch/select-free hot path
__global__ void __launch_bounds__(256) k_loss(const float4* __restrict__ conf4) {
    float acc = 0.f;
    int stride = gridDim.x * blockDim.x;
    for (int i = blockIdx.x * blockDim.x + threadIdx.x; i < TOTAL4; i += stride) {
        unsigned bp = (unsigned)i / 20u;           // 20 float4 per prior
        if (g_valid[bp]) {
            float4 x = conf4[i];
            acc += g0raw(x.x) + g0raw(x.y) + g0raw(x.z) + g0raw(x.w);
        }
    }
    // block reduction
    #pragma unroll
    for (int o = 16; o; o >>= 1) acc += __shfl_down_sync(0xFFFFFFFFu, acc, o);
    __shared__ float s_a[8];
    int wid = threadIdx.x >> 5, lane = threadIdx.x & 31;
    if (lane == 0) s_a[wid] = acc;
    __syncthreads();
    if (wid == 0) {
        acc = (lane < 8) ? s_a[lane] : 0.f;
        #pragma unroll
        for (int o = 4; o; o >>= 1) acc += __shfl_down_sync(0xFFFFFFFFu, acc, o);
        if (lane == 0) atomicAdd(&g_sum_lcraw, acc);
    }
}

// finalize AND reset all scratch state for the next replay
__global__ void k_final(float* __restrict__ out) {
    int i = threadIdx.x;
    if (i == 0) {
        float pn = fmaxf((float)g_poscnt, 1.0f);
        out[0] = g_sum_ll / (pn * 4.0f);
        out[1] = (0.75f * g_sum_lcraw + g_sum_corr) / pn;
        g_sum_ll = 0.f; g_sum_lcraw = 0.f; g_sum_corr = 0.f; g_poscnt = 0;
    }
    if (i < B * O) g_bestprior[i] = 0ull;
}

// ---------------- launch ----------------
extern "C" void kernel_launch(void* const* d_in, const int* in_sizes, int n_in,
                              void* d_out, int out_size) {
    const float4* loc4    = (const float4*)d_in[0];   // (B,P,4)  f32
    const float4* conf4   = (const float4*)d_in[1];   // (B,P,80) f32
    const float4* priors4 = (const float4*)d_in[2];   // (P,4)    f32
    const float*  targets = (const float*)d_in[3];    // (B,O,5)  f32
    float* out = (float*)d_out;

    dim3 mg(P / 256, B);
    k_match<<<mg, 256>>>(priors4, targets);
    k_override<<<1, 32>>>();
    k_meta<<<(B * P) / 256, 256>>>(loc4, priors4, targets, (const float*)d_in[1]);
    k_loss<<<1216, 256>>>(conf4);                     // ~one full wave, grid-stride
    k_final<<<1, 512>>>(out);
}